// round 17
// baseline (speedup 1.0000x reference)
#include <cuda_runtime.h>
#include <cuda_fp16.h>
#include <cstdint>

#define BATCH 256
#define SEQ   1024
#define HID   512
#define LTILE 128
#define NH    256

// ------------ device scratch ------------
__device__ __align__(16) __half g_wsh[HID * HID];
__device__ float g_projh[BATCH * HID];
__device__ float g_scores2[2][BATCH * SEQ];
__device__ float g_ctxpart[8][BATCH * HID];

// ------------ helpers ------------
__device__ __forceinline__ uint32_t smem_u32(const void* p) {
    uint32_t a;
    asm("{ .reg .u64 t; cvta.to.shared.u64 t, %1; cvt.u32.u64 %0, t; }" : "=r"(a) : "l"(p));
    return a;
}
__device__ __forceinline__ float fast_tanh(float x) {
    float y; asm("tanh.approx.f32 %0, %1;" : "=f"(y) : "f"(x)); return y;
}
__device__ __forceinline__ void ldsm4(uint32_t* r, uint32_t addr) {
    asm volatile("ldmatrix.sync.aligned.m8n8.x4.shared.b16 {%0,%1,%2,%3}, [%4];"
        : "=r"(r[0]), "=r"(r[1]), "=r"(r[2]), "=r"(r[3]) : "r"(addr));
}
__device__ __forceinline__ void mma16816h(uint32_t* c, const uint32_t* a, const uint32_t* b) {
    asm volatile("mma.sync.aligned.m16n8k16.row.col.f16.f16.f16.f16 "
        "{%0,%1}, {%2,%3,%4,%5}, {%6,%7}, {%0,%1};"
        : "+r"(c[0]), "+r"(c[1])
        : "r"(a[0]), "r"(a[1]), "r"(a[2]), "r"(a[3]), "r"(b[0]), "r"(b[1]));
}
__device__ __forceinline__ void cp16(uint32_t dst, const void* src) {
    asm volatile("cp.async.cg.shared.global [%0], [%1], 16;" :: "r"(dst), "l"(src) : "memory");
}
#define CP_COMMIT() asm volatile("cp.async.commit_group;" ::: "memory")

__device__ __forceinline__ uint32_t packh2(float a, float b) {
    __half2 t = __floats2half2_rn(a, b);
    return *reinterpret_cast<uint32_t*>(&t);
}
__device__ __forceinline__ void cvt8(const float* src, __half* dst, size_t i) {
    float4 x0 = *reinterpret_cast<const float4*>(src + i);
    float4 x1 = *reinterpret_cast<const float4*>(src + i + 4);
    uint4 o;
    o.x = packh2(x0.x, x0.y);
    o.y = packh2(x0.z, x0.w);
    o.z = packh2(x1.x, x1.y);
    o.w = packh2(x1.z, x1.w);
    *reinterpret_cast<uint4*>(dst + i) = o;
}

// ------------ K0: cvt_ws (2 launches so scores lands at idx 3) ------------
__global__ void __launch_bounds__(256)
cvt_ws_kernel(const float* __restrict__ Ws, int off) {
    cvt8(Ws, g_wsh, ((size_t)(blockIdx.x + off) * 256 + threadIdx.x) * 8);
}

// ------------ K1: proj_h ------------
__global__ void __launch_bounds__(256)
projh_kernel(const float* __restrict__ dec, const float* __restrict__ Wh) {
    __shared__ float4 dsm[8][HID / 4];
    const int half = blockIdx.x, bg = blockIdx.y, tid = threadIdx.x;
    for (int i = tid; i < 8 * (HID / 4); i += 256) {
        int bb = i >> 7, k4 = i & 127;
        dsm[bb][k4] = reinterpret_cast<const float4*>(dec + (size_t)(bg * 8 + bb) * HID)[k4];
    }
    __syncthreads();
    const int h = half * 256 + tid;
    const float4* wr = reinterpret_cast<const float4*>(Wh + (size_t)h * HID);
    float acc[8];
#pragma unroll
    for (int bb = 0; bb < 8; ++bb) acc[bb] = 0.f;
    for (int k4 = 0; k4 < HID / 4; ++k4) {
        float4 w = wr[k4];
#pragma unroll
        for (int bb = 0; bb < 8; ++bb) {
            float4 d = dsm[bb][k4];
            acc[bb] += w.x * d.x + w.y * d.y + w.z * d.z + w.w * d.w;
        }
    }
#pragma unroll
    for (int bb = 0; bb < 8; ++bb)
        g_projh[(size_t)(bg * 8 + bb) * HID + h] = acc[bb];
}

// ------------ K2: fused scores GEMM ------------
// 256 threads (8 warps, 2M x 4N, warp tile 64x64), CTA M=128 x N=256,
// KTILE=64, 2-stage ring, single barrier/iter, fp16 accumulators.
// A path software-pipelined: LDG fp32 (chunk kc+1) issued right after the
// barrier, cvt+STS deferred until AFTER chunk kc's MMAs -> LDG latency
// hidden behind ~2000 cyc of tensor work.
#define PAD_B   144
#define A_BYTES (128 * PAD_B)           // 18432
#define B_BYTES (256 * PAD_B)           // 36864
#define STAGE   (A_BYTES + B_BYTES)     // 55296
#define OFF_PROJH 0
#define OFF_V     1024
#define OFF_SC    2048
#define OFF_TILES 4096
#define K2_SMEM   (OFF_TILES + 2 * STAGE)   // 114688

__global__ void __launch_bounds__(256, 2)
scores_kernel(const float* __restrict__ enc, const float* __restrict__ v) {
    extern __shared__ char smem[];
    const uint32_t sb = smem_u32(smem);
    const int tid = threadIdx.x, lane = tid & 31, w = tid >> 5;
    const int wm = w & 1, wn = w >> 1;            // 2 M-warps x 4 N-warps
    const int hhalf = blockIdx.x & 1, ltile = blockIdx.x >> 1, b = blockIdx.y;

    float* projh_sm = reinterpret_cast<float*>(smem + OFF_PROJH);
    float* v_sm     = reinterpret_cast<float*>(smem + OFF_V);
    projh_sm[tid] = g_projh[(size_t)b * HID + hhalf * NH + tid];
    v_sm[tid]     = v[hhalf * NH + tid];

    const float*  Asrc = enc + ((size_t)b * SEQ + (size_t)ltile * LTILE) * HID;
    const __half* Bsrc = g_wsh + (size_t)hhalf * NH * HID;

    // per-thread A-granule coords (4 granules: rows r0.., segs s0..)
    const int ar = tid >> 3;          // 0..31 row base (stride 32 across j)
    const int as = tid & 7;           // seg
    const uint32_t a_sts = (uint32_t)(ar * PAD_B + as * 16);

    const int rowA  = wm * 64 + (lane & 7) + ((lane >> 3) & 1) * 8;
    const int koffA = (lane >> 4) * 16;
    const uint32_t aoff = (uint32_t)(rowA * PAD_B + koffA);
    const int rowB  = wn * 64 + (lane & 7) + (lane >> 4) * 8;
    const int koffB = ((lane >> 3) & 1) * 16;
    const uint32_t boff = (uint32_t)(A_BYTES + rowB * PAD_B + koffB);

    uint32_t c16[4][8][2];   // 64 regs
#pragma unroll
    for (int mf = 0; mf < 4; ++mf)
#pragma unroll
        for (int nf = 0; nf < 8; ++nf)
            c16[mf][nf][0] = c16[mf][nf][1] = 0u;

    float4 stg[8];           // 32 staging regs (4 granules x 2 float4)

    auto ldg_a = [&](int kc) {
#pragma unroll
        for (int j = 0; j < 4; ++j) {
            const float4* s = reinterpret_cast<const float4*>(
                Asrc + (size_t)(ar + j * 32) * HID + kc * 64 + as * 8);
            stg[2 * j]     = s[0];
            stg[2 * j + 1] = s[1];
        }
    };
    auto sts_a = [&](int buf) {
        char* base = smem + OFF_TILES + (uint32_t)buf * STAGE;
#pragma unroll
        for (int j = 0; j < 4; ++j) {
            uint4 o;
            o.x = packh2(stg[2 * j].x,     stg[2 * j].y);
            o.y = packh2(stg[2 * j].z,     stg[2 * j].w);
            o.z = packh2(stg[2 * j + 1].x, stg[2 * j + 1].y);
            o.w = packh2(stg[2 * j + 1].z, stg[2 * j + 1].w);
            *reinterpret_cast<uint4*>(base + a_sts + (uint32_t)(j * 32 * PAD_B)) = o;
        }
    };
    auto cpb = [&](int kc, int buf) {
        uint32_t tb = sb + OFF_TILES + (uint32_t)buf * STAGE;
#pragma unroll
        for (int j = 0; j < 8; ++j) {
            int idx = tid + j * 256;
            int r = idx >> 3, seg = idx & 7;
            cp16(tb + A_BYTES + (uint32_t)(r * PAD_B + seg * 16),
                 Bsrc + (size_t)r * HID + kc * 64 + seg * 8);
        }
        CP_COMMIT();
    };

    // prologue: chunk 0 fully staged
    ldg_a(0);
    cpb(0, 0);
    sts_a(0);

#pragma unroll 1
    for (int kc = 0; kc < 8; ++kc) {
        asm volatile("cp.async.wait_group 0;" ::: "memory");
        __syncthreads();   // chunk kc visible (B cp.async + A STS); also all
                           // warps done with iter kc-1's ldsm of buf (kc+1)&1
        if (kc < 7) {
            ldg_a(kc + 1);       // fp32 loads in flight across the MMA phase
            cpb(kc + 1, (kc + 1) & 1);
        }
        uint32_t tb = sb + OFF_TILES + (uint32_t)(kc & 1) * STAGE;
#pragma unroll
        for (int kk = 0; kk < 4; ++kk) {
            uint32_t a[4][4];
#pragma unroll
            for (int mf = 0; mf < 4; ++mf)
                ldsm4(a[mf], tb + aoff + (uint32_t)mf * (16 * PAD_B) + kk * 32);
#pragma unroll
            for (int gi = 0; gi < 4; ++gi) {
                uint32_t bf[4];
                ldsm4(bf, tb + boff + (uint32_t)gi * (16 * PAD_B) + kk * 32);
#pragma unroll
                for (int mf = 0; mf < 4; ++mf) {
                    mma16816h(c16[mf][gi * 2 + 0], a[mf], bf);
                    mma16816h(c16[mf][gi * 2 + 1], a[mf], bf + 2);
                }
            }
        }
        if (kc < 7) sts_a((kc + 1) & 1);   // WAR-safe: see barrier comment
    }

    float part[4][2];
#pragma unroll
    for (int mf = 0; mf < 4; ++mf) part[mf][0] = part[mf][1] = 0.f;
#pragma unroll
    for (int mf = 0; mf < 4; ++mf)
#pragma unroll
        for (int nf = 0; nf < 8; ++nf)
#pragma unroll
            for (int rp = 0; rp < 2; ++rp) {
                float2 f = __half22float2(*reinterpret_cast<__half2*>(&c16[mf][nf][rp]));
                int h0 = wn * 64 + nf * 8 + (lane & 3) * 2;
                float p0 = f.x + projh_sm[h0];
                float p1 = f.y + projh_sm[h0 + 1];
                part[mf][rp] += v_sm[h0] * fast_tanh(p0) + v_sm[h0 + 1] * fast_tanh(p1);
            }
    float* sc = reinterpret_cast<float*>(smem + OFF_SC);
#pragma unroll
    for (int mf = 0; mf < 4; ++mf)
#pragma unroll
        for (int rp = 0; rp < 2; ++rp) {
            float val = part[mf][rp];
            val += __shfl_xor_sync(0xffffffffu, val, 1);
            val += __shfl_xor_sync(0xffffffffu, val, 2);
            if ((lane & 3) == 0)
                sc[wn * 128 + wm * 64 + mf * 16 + rp * 8 + (lane >> 2)] = val;
        }
    __syncthreads();
    if (tid < 128)
        g_scores2[hhalf][(size_t)b * SEQ + ltile * LTILE + tid] =
            (sc[tid] + sc[128 + tid]) + (sc[256 + tid] + sc[384 + tid]);
}

// ------------ K3: softmax -> alpha ------------
__global__ void __launch_bounds__(256)
softmax_kernel(float* __restrict__ alpha) {
    __shared__ float red[8];
    const int b = blockIdx.x, tid = threadIdx.x, wid = tid >> 5, lid = tid & 31;
    float s[4];
#pragma unroll
    for (int i = 0; i < 4; ++i) {
        size_t l = (size_t)b * SEQ + tid + i * 256;
        s[i] = g_scores2[0][l] + g_scores2[1][l];
    }
    float m = fmaxf(fmaxf(s[0], s[1]), fmaxf(s[2], s[3]));
#pragma unroll
    for (int o = 16; o; o >>= 1) m = fmaxf(m, __shfl_xor_sync(0xffffffffu, m, o));
    if (lid == 0) red[wid] = m;
    __syncthreads();
    m = red[0];
#pragma unroll
    for (int i = 1; i < 8; ++i) m = fmaxf(m, red[i]);
    __syncthreads();
    float e[4], sum = 0.f;
#pragma unroll
    for (int i = 0; i < 4; ++i) { e[i] = __expf(s[i] - m); sum += e[i]; }
#pragma unroll
    for (int o = 16; o; o >>= 1) sum += __shfl_xor_sync(0xffffffffu, sum, o);
    if (lid == 0) red[wid] = sum;
    __syncthreads();
    sum = 0.f;
#pragma unroll
    for (int i = 0; i < 8; ++i) sum += red[i];
    float inv = 1.0f / sum;
#pragma unroll
    for (int i = 0; i < 4; ++i)
        alpha[(size_t)b * SEQ + tid + i * 256] = e[i] * inv;
}

// ------------ K4: context partials, 8-way l-split, fp32 enc ------------
__global__ void __launch_bounds__(256)
context_part_kernel(const float* __restrict__ enc, const float* __restrict__ alpha) {
    __shared__ float al[128];
    __shared__ float red[4][HID];
    const int lc = blockIdx.x, b = blockIdx.y, tid = threadIdx.x;
    if (tid < 128) al[tid] = alpha[(size_t)b * SEQ + lc * 128 + tid];
    __syncthreads();
    const int cg = tid & 63;
    const int ph = tid >> 6;
    const float* ep = enc + ((size_t)b * SEQ + lc * 128) * HID + cg * 8;
    float acc[8];
#pragma unroll
    for (int j = 0; j < 8; ++j) acc[j] = 0.f;
#pragma unroll 4
    for (int l = ph; l < 128; l += 4) {
        const float4* p4 = reinterpret_cast<const float4*>(ep + (size_t)l * HID);
        float4 u0 = p4[0], u1 = p4[1];
        float a = al[l];
        acc[0] += a * u0.x; acc[1] += a * u0.y;
        acc[2] += a * u0.z; acc[3] += a * u0.w;
        acc[4] += a * u1.x; acc[5] += a * u1.y;
        acc[6] += a * u1.z; acc[7] += a * u1.w;
    }
#pragma unroll
    for (int j = 0; j < 8; ++j) red[ph][cg * 8 + j] = acc[j];
    __syncthreads();
    for (int e = tid; e < HID; e += 256)
        g_ctxpart[lc][(size_t)b * HID + e] =
            (red[0][e] + red[1][e]) + (red[2][e] + red[3][e]);
}

// ------------ K5: reduce context partials ------------
__global__ void __launch_bounds__(512)
context_reduce_kernel(float* __restrict__ ctx) {
    const size_t i = (size_t)blockIdx.x * HID + threadIdx.x;
    float s = 0.f;
#pragma unroll
    for (int p = 0; p < 8; ++p) s += g_ctxpart[p][i];
    ctx[i] = s;
}

// ------------ launch ------------
extern "C" void kernel_launch(void* const* d_in, const int* in_sizes, int n_in,
                              void* d_out, int out_size) {
    const float* dec = (const float*)d_in[0];
    const float* enc = (const float*)d_in[1];
    const float* Wh  = (const float*)d_in[2];
    const float* Ws  = (const float*)d_in[3];
    const float* v   = (const float*)d_in[4];
    float* out   = (float*)d_out;
    float* ctx   = out;
    float* alpha = out + BATCH * HID;

    cudaFuncSetAttribute(scores_kernel, cudaFuncAttributeMaxDynamicSharedMemorySize, K2_SMEM);

    cvt_ws_kernel<<<64, 256>>>(Ws, 0);                                  // idx 0
    cvt_ws_kernel<<<64, 256>>>(Ws, 64);                                 // idx 1
    projh_kernel<<<dim3(2, 32), 256>>>(dec, Wh);                        // idx 2
    scores_kernel<<<dim3(16, BATCH), 256, K2_SMEM>>>(enc, v);           // idx 3 (profiled)
    softmax_kernel<<<BATCH, 256>>>(alpha);
    context_part_kernel<<<dim3(8, BATCH), 256>>>(enc, alpha);
    context_reduce_kernel<<<BATCH, 512>>>(ctx);
}